// round 1
// baseline (speedup 1.0000x reference)
#include <cuda_runtime.h>
#include <cstdint>

#define TGT 1024
#define SRC 1024
#define BSZb 4
#define EMB 1024
#define NH 16
#define HD 64

// -------- device scratch (allocation-free rule: __device__ globals) --------
__device__ float g_q[BSZb * NH * TGT * HD];        // (b,h,t,d) scaled
__device__ float g_k[BSZb * NH * SRC * HD];        // (b,h,s,d)
__device__ float g_vt[BSZb * NH * HD * SRC];       // (b,h,d,s)  (transposed V)
__device__ float g_scores[(size_t)BSZb * NH * TGT * SRC]; // 256 MB: scores -> masked P
__device__ float g_ctx[TGT * BSZb * EMB];          // (t,b,e)

// ---------------------------------------------------------------------------
// Generic SGEMM: C[m,n] = sum_k A[m,k]*B[n,k]  (both operands k-contiguous)
// MODE: 0=scores  1=Qproj  2=Kproj  3=Vproj(transpose)  4=PV->ctx  5=outproj
// ---------------------------------------------------------------------------
template <int BM, int BN, int BK, int TM, int TN, int MODE>
__global__ void __launch_bounds__((BM / TM) * (BN / TN))
gemm_kernel(const float* __restrict__ A, int lda,
            const float* __restrict__ B, int ldb,
            const float* __restrict__ bias,
            float* __restrict__ C,
            int M, int N, int K)
{
    constexpr int THREADS = (BM / TM) * (BN / TN);
    __shared__ float As[BK][BM];
    __shared__ float Bs[BK][BN];

    const int z = blockIdx.z;

    const float* Ap;
    const float* Bp;
    if constexpr (MODE == 0) {
        Ap = g_q + (size_t)z * TGT * HD;
        Bp = g_k + (size_t)z * SRC * HD;
    } else if constexpr (MODE == 4) {
        Ap = g_scores + (size_t)z * TGT * SRC;
        Bp = g_vt + (size_t)z * HD * SRC;
    } else if constexpr (MODE == 5) {
        Ap = g_ctx;
        Bp = B;
    } else {
        Ap = A;
        Bp = B;
    }

    const int bm = blockIdx.y * BM;
    const int bn = blockIdx.x * BN;
    const int tid = threadIdx.x;
    const int tx = tid % (BN / TN);
    const int ty = tid / (BN / TN);

    float acc[TM][TN];
#pragma unroll
    for (int i = 0; i < TM; i++)
#pragma unroll
        for (int j = 0; j < TN; j++) acc[i][j] = 0.0f;

    for (int k0 = 0; k0 < K; k0 += BK) {
        // load A tile (transposed into As[k][m])
#pragma unroll
        for (int i = tid * 4; i < BM * BK; i += THREADS * 4) {
            int r = i / BK, c = i % BK;
            float4 v = *(const float4*)(Ap + (size_t)(bm + r) * lda + k0 + c);
            As[c + 0][r] = v.x; As[c + 1][r] = v.y;
            As[c + 2][r] = v.z; As[c + 3][r] = v.w;
        }
        // load B tile (transposed into Bs[k][n])
#pragma unroll
        for (int i = tid * 4; i < BN * BK; i += THREADS * 4) {
            int r = i / BK, c = i % BK;
            float4 v = *(const float4*)(Bp + (size_t)(bn + r) * ldb + k0 + c);
            Bs[c + 0][r] = v.x; Bs[c + 1][r] = v.y;
            Bs[c + 2][r] = v.z; Bs[c + 3][r] = v.w;
        }
        __syncthreads();

#pragma unroll
        for (int k = 0; k < BK; k++) {
            float a[TM], b[TN];
#pragma unroll
            for (int i = 0; i < TM; i += 4) {
                float4 v = *(const float4*)(&As[k][ty * TM + i]);
                a[i] = v.x; a[i + 1] = v.y; a[i + 2] = v.z; a[i + 3] = v.w;
            }
#pragma unroll
            for (int j = 0; j < TN; j += 4) {
                float4 v = *(const float4*)(&Bs[k][tx * TN + j]);
                b[j] = v.x; b[j + 1] = v.y; b[j + 2] = v.z; b[j + 3] = v.w;
            }
#pragma unroll
            for (int i = 0; i < TM; i++)
#pragma unroll
                for (int j = 0; j < TN; j++) acc[i][j] += a[i] * b[j];
        }
        __syncthreads();
    }

    // epilogue
#pragma unroll
    for (int i = 0; i < TM; i++) {
        const int m = bm + ty * TM + i;
#pragma unroll
        for (int j = 0; j < TN; j++) {
            const int n = bn + tx * TN + j;
            float v = acc[i][j];
            if constexpr (MODE == 1) {
                v = (v + bias[n]) * 0.125f;  // HD^-0.5
                int t = m >> 2, b = m & 3, h = n >> 6, d = n & 63;
                g_q[(((size_t)(b * NH + h)) * TGT + t) * HD + d] = v;
            } else if constexpr (MODE == 2) {
                v += bias[n];
                int s = m >> 2, b = m & 3, h = n >> 6, d = n & 63;
                g_k[(((size_t)(b * NH + h)) * SRC + s) * HD + d] = v;
            } else if constexpr (MODE == 3) {
                v += bias[n];
                int s = m >> 2, b = m & 3, h = n >> 6, d = n & 63;
                g_vt[(((size_t)(b * NH + h)) * HD + d) * SRC + s] = v;
            } else if constexpr (MODE == 0) {
                g_scores[(size_t)z * TGT * SRC + (size_t)m * SRC + n] = v;
            } else if constexpr (MODE == 4) {
                int b = z / NH, h = z % NH;
                g_ctx[((size_t)m * BSZb + b) * EMB + h * HD + n] = v;
            } else { // MODE == 5
                C[(size_t)m * EMB + n] = v + bias[n];
            }
        }
    }
}

// ---------------------------------------------------------------------------
// softmax (per row over s) -> multiply hard mask -> write masked P in place,
// accumulate head-average into avg_out. Block = (t,b), 256 threads, loop heads.
// ---------------------------------------------------------------------------
__global__ void __launch_bounds__(256)
softmax_mask_avg_kernel(const float* __restrict__ hard, float* __restrict__ avg_out)
{
    const int t = blockIdx.x;
    const int b = blockIdx.y;
    const int tid = threadIdx.x;
    __shared__ float red[8];

    const float* mrow = hard + ((size_t)b * TGT + t) * SRC;
    float mask[4], avg[4] = {0.f, 0.f, 0.f, 0.f};
#pragma unroll
    for (int i = 0; i < 4; i++) mask[i] = mrow[tid + i * 256];

    for (int h = 0; h < NH; h++) {
        float* row = g_scores + ((size_t)(b * NH + h) * TGT + t) * SRC;
        float v[4];
#pragma unroll
        for (int i = 0; i < 4; i++) v[i] = row[tid + i * 256];

        float m = fmaxf(fmaxf(v[0], v[1]), fmaxf(v[2], v[3]));
#pragma unroll
        for (int o = 16; o; o >>= 1) m = fmaxf(m, __shfl_xor_sync(0xffffffffu, m, o));
        if ((tid & 31) == 0) red[tid >> 5] = m;
        __syncthreads();
        m = fmaxf(fmaxf(fmaxf(red[0], red[1]), fmaxf(red[2], red[3])),
                  fmaxf(fmaxf(red[4], red[5]), fmaxf(red[6], red[7])));
        __syncthreads();

        float e[4], s = 0.f;
#pragma unroll
        for (int i = 0; i < 4; i++) { e[i] = __expf(v[i] - m); s += e[i]; }
#pragma unroll
        for (int o = 16; o; o >>= 1) s += __shfl_xor_sync(0xffffffffu, s, o);
        if ((tid & 31) == 0) red[tid >> 5] = s;
        __syncthreads();
        s = red[0] + red[1] + red[2] + red[3] + red[4] + red[5] + red[6] + red[7];
        __syncthreads();

        const float inv = 1.0f / s;
#pragma unroll
        for (int i = 0; i < 4; i++) {
            float p = e[i] * inv * mask[i];
            row[tid + i * 256] = p;
            avg[i] += p;
        }
    }

    float* arow = avg_out + ((size_t)b * TGT + t) * SRC;
#pragma unroll
    for (int i = 0; i < 4; i++) arow[tid + i * 256] = avg[i] * (1.0f / NH);
}

// ---------------------------------------------------------------------------
extern "C" void kernel_launch(void* const* d_in, const int* in_sizes, int n_in,
                              void* d_out, int out_size)
{
    const float* query = (const float*)d_in[0];  // (T,B,E)
    const float* key   = (const float*)d_in[1];  // (S,B,E)
    const float* hard  = (const float*)d_in[2];  // (B,T,S)
    const float* W     = (const float*)d_in[3];  // (3E,E)
    const float* bias  = (const float*)d_in[4];  // (3E,)
    const float* Wo    = (const float*)d_in[5];  // (E,E)
    const float* bo    = (const float*)d_in[6];  // (E,)
    float* out = (float*)d_out;                  // [T*B*E] out, then [B*T*S] avg
    float* avg_out = out + (size_t)TGT * BSZb * EMB;

    const int MTB = TGT * BSZb;  // 4096

    // 1..3: QKV projections (fp32 SGEMM, scatter epilogues)
    {
        dim3 grid(EMB / 128, MTB / 128);
        gemm_kernel<128, 128, 16, 8, 8, 1><<<grid, 256>>>(
            query, EMB, W, EMB, bias, nullptr, MTB, EMB, EMB);
        gemm_kernel<128, 128, 16, 8, 8, 2><<<grid, 256>>>(
            key, EMB, W + (size_t)EMB * EMB, EMB, bias + EMB, nullptr, MTB, EMB, EMB);
        gemm_kernel<128, 128, 16, 8, 8, 3><<<grid, 256>>>(
            key, EMB, W + (size_t)2 * EMB * EMB, EMB, bias + 2 * EMB, nullptr, MTB, EMB, EMB);
    }

    // 4: scores = Q @ K^T per (b,h)
    {
        dim3 grid(SRC / 128, TGT / 128, BSZb * NH);
        gemm_kernel<128, 128, 16, 8, 8, 0><<<grid, 256>>>(
            nullptr, HD, nullptr, HD, nullptr, nullptr, TGT, SRC, HD);
    }

    // 5: softmax + mask + head-average
    {
        dim3 grid(TGT, BSZb);
        softmax_mask_avg_kernel<<<grid, 256>>>(hard, avg_out);
    }

    // 6: ctx = P @ V per (b,h)
    {
        dim3 grid(HD / 64, TGT / 128, BSZb * NH);
        gemm_kernel<128, 64, 16, 8, 8, 4><<<grid, 128>>>(
            nullptr, SRC, nullptr, SRC, nullptr, nullptr, TGT, HD, SRC);
    }

    // 7: out projection
    {
        dim3 grid(EMB / 128, MTB / 128);
        gemm_kernel<128, 128, 16, 8, 8, 5><<<grid, 256>>>(
            nullptr, EMB, Wo, EMB, bo, out, MTB, EMB, EMB);
    }
}

// round 3
// speedup vs baseline: 2.4666x; 2.4666x over previous
#include <cuda_runtime.h>
#include <cstdint>

#define TGT 1024
#define SRC 1024
#define BSZb 4
#define EMB 1024
#define NH 16
#define HD 64

// -------- device scratch (allocation-free rule: __device__ globals) --------
__device__ float g_q[BSZb * NH * TGT * HD];        // (b,h,t,d) scaled
__device__ float g_k[BSZb * NH * SRC * HD];        // (b,h,s,d)
__device__ float g_vt[BSZb * NH * HD * SRC];       // (b,h,d,s)
__device__ float g_scores[(size_t)BSZb * NH * TGT * SRC]; // scores -> masked P
__device__ float g_ctx[TGT * BSZb * EMB];          // (t,b,e)

__device__ __forceinline__ uint32_t f2tf(float x) {
    uint32_t r;
    asm("cvt.rna.tf32.f32 %0, %1;" : "=r"(r) : "f"(x));
    return r;
}

__device__ __forceinline__ void mma8(float* d, uint32_t a0, uint32_t a1,
                                     uint32_t a2, uint32_t a3,
                                     uint32_t b0, uint32_t b1) {
    asm volatile(
        "mma.sync.aligned.m16n8k8.row.col.f32.tf32.tf32.f32 "
        "{%0,%1,%2,%3}, {%4,%5,%6,%7}, {%8,%9}, {%0,%1,%2,%3};"
        : "+f"(d[0]), "+f"(d[1]), "+f"(d[2]), "+f"(d[3])
        : "r"(a0), "r"(a1), "r"(a2), "r"(a3), "r"(b0), "r"(b1));
}

// ---------------------------------------------------------------------------
// tf32 mma.sync GEMM: C[m,n] = sum_k A[m,k]*B[n,k] (both k-contiguous)
// MODE: 0=scores 1=Qproj 2=Kproj 3=Vproj(transpose) 4=PV->ctx 5=outproj
// ---------------------------------------------------------------------------
template <int BM, int BN, int WM, int WN, int MODE>
__global__ void __launch_bounds__(256)
mma_gemm(const float* __restrict__ A, int lda,
         const float* __restrict__ B, int ldb,
         const float* __restrict__ bias,
         float* __restrict__ C, int K)
{
    constexpr int WTM = BM / WM, WTN = BN / WN;
    constexpr int MT = WTM / 16, NT = WTN / 8;
    constexpr int AG = BM / 64, BG = BN / 64;  // float4 loads/thread/chunk

    __shared__ uint32_t As[2][BM][20];
    __shared__ uint32_t Bs[2][BN][20];

    const int z = blockIdx.z;
    const float* Ap;
    const float* Bp;
    if constexpr (MODE == 0) {
        Ap = g_q + (size_t)z * TGT * HD;
        Bp = g_k + (size_t)z * SRC * HD;
    } else if constexpr (MODE == 4) {
        Ap = g_scores + (size_t)z * TGT * SRC;
        Bp = g_vt + (size_t)z * HD * SRC;
    } else if constexpr (MODE == 5) {
        Ap = g_ctx;
        Bp = B;
    } else {
        Ap = A;
        Bp = B;
    }

    const int bm = blockIdx.y * BM;
    const int bn = blockIdx.x * BN;
    const int tid = threadIdx.x;
    const int lane = tid & 31;
    const int wid = tid >> 5;
    const int wm = wid / WN;
    const int wn = wid % WN;

    float acc[MT][NT][4];
#pragma unroll
    for (int i = 0; i < MT; i++)
#pragma unroll
        for (int j = 0; j < NT; j++)
#pragma unroll
            for (int q = 0; q < 4; q++) acc[i][j][q] = 0.0f;

    const float* ag0 = Ap + (size_t)bm * lda;
    const float* bg0 = Bp + (size_t)bn * ldb;
    const int NC = K / 16;

    // --- load chunk 0 ---
#pragma unroll
    for (int it = 0; it < AG; it++) {
        int g = tid + it * 256, r = g >> 2, kq = g & 3;
        float4 v = *(const float4*)(ag0 + (size_t)r * lda + kq * 4);
        uint4 t = { f2tf(v.x), f2tf(v.y), f2tf(v.z), f2tf(v.w) };
        *(uint4*)&As[0][r][kq * 4] = t;
    }
#pragma unroll
    for (int it = 0; it < BG; it++) {
        int g = tid + it * 256, r = g >> 2, kq = g & 3;
        float4 v = *(const float4*)(bg0 + (size_t)r * ldb + kq * 4);
        uint4 t = { f2tf(v.x), f2tf(v.y), f2tf(v.z), f2tf(v.w) };
        *(uint4*)&Bs[0][r][kq * 4] = t;
    }
    __syncthreads();

    for (int ch = 0; ch < NC; ch++) {
        const int buf = ch & 1;

        // prefetch next chunk into registers
        float4 pa[AG], pb[BG];
        if (ch + 1 < NC) {
            const float* ag = ag0 + (ch + 1) * 16;
#pragma unroll
            for (int it = 0; it < AG; it++) {
                int g = tid + it * 256, r = g >> 2, kq = g & 3;
                pa[it] = *(const float4*)(ag + (size_t)r * lda + kq * 4);
            }
            const float* bg = bg0 + (ch + 1) * 16;
#pragma unroll
            for (int it = 0; it < BG; it++) {
                int g = tid + it * 256, r = g >> 2, kq = g & 3;
                pb[it] = *(const float4*)(bg + (size_t)r * ldb + kq * 4);
            }
        }

        // compute on current buffer
#pragma unroll
        for (int ks = 0; ks < 16; ks += 8) {
            uint32_t bf[NT][2];
#pragma unroll
            for (int nt = 0; nt < NT; nt++) {
                int n = wn * WTN + nt * 8 + (lane >> 2);
                bf[nt][0] = Bs[buf][n][ks + (lane & 3)];
                bf[nt][1] = Bs[buf][n][ks + 4 + (lane & 3)];
            }
#pragma unroll
            for (int mt = 0; mt < MT; mt++) {
                int m = wm * WTM + mt * 16 + (lane >> 2);
                uint32_t a0 = As[buf][m][ks + (lane & 3)];
                uint32_t a1 = As[buf][m + 8][ks + (lane & 3)];
                uint32_t a2 = As[buf][m][ks + 4 + (lane & 3)];
                uint32_t a3 = As[buf][m + 8][ks + 4 + (lane & 3)];
#pragma unroll
                for (int nt = 0; nt < NT; nt++)
                    mma8(acc[mt][nt], a0, a1, a2, a3, bf[nt][0], bf[nt][1]);
            }
        }

        // store prefetched chunk into other buffer
        if (ch + 1 < NC) {
            const int nb = buf ^ 1;
#pragma unroll
            for (int it = 0; it < AG; it++) {
                int g = tid + it * 256, r = g >> 2, kq = g & 3;
                uint4 t = { f2tf(pa[it].x), f2tf(pa[it].y), f2tf(pa[it].z), f2tf(pa[it].w) };
                *(uint4*)&As[nb][r][kq * 4] = t;
            }
#pragma unroll
            for (int it = 0; it < BG; it++) {
                int g = tid + it * 256, r = g >> 2, kq = g & 3;
                uint4 t = { f2tf(pb[it].x), f2tf(pb[it].y), f2tf(pb[it].z), f2tf(pb[it].w) };
                *(uint4*)&Bs[nb][r][kq * 4] = t;
            }
            __syncthreads();
        }
    }

    // --- epilogue ---
#pragma unroll
    for (int mt = 0; mt < MT; mt++) {
#pragma unroll
        for (int nt = 0; nt < NT; nt++) {
            const int r0 = bm + wm * WTM + mt * 16 + (lane >> 2);
            const int c0 = bn + wn * WTN + nt * 8 + 2 * (lane & 3);
            const float* a4 = acc[mt][nt];

#pragma unroll
            for (int half = 0; half < 2; half++) {
                const int r = r0 + half * 8;
                const float v0 = a4[half * 2 + 0];
                const float v1 = a4[half * 2 + 1];

                if constexpr (MODE == 0) {
                    float2 w = { v0, v1 };
                    *(float2*)(g_scores + (size_t)z * TGT * SRC + (size_t)r * SRC + c0) = w;
                } else if constexpr (MODE == 4) {
                    int b = z >> 4, h = z & 15;
                    float2 w = { v0, v1 };
                    *(float2*)(g_ctx + ((size_t)r * BSZb + b) * EMB + h * HD + c0) = w;
                } else if constexpr (MODE == 5) {
                    float2 w = { v0 + bias[c0], v1 + bias[c0 + 1] };
                    *(float2*)(C + (size_t)r * EMB + c0) = w;
                } else if constexpr (MODE == 1) {
                    int t = r >> 2, b = r & 3, h = c0 >> 6, d = c0 & 63;
                    float2 w = { (v0 + bias[c0]) * 0.125f, (v1 + bias[c0 + 1]) * 0.125f };
                    *(float2*)(g_q + (((size_t)(b * NH + h)) * TGT + t) * HD + d) = w;
                } else if constexpr (MODE == 2) {
                    int s = r >> 2, b = r & 3, h = c0 >> 6, d = c0 & 63;
                    float2 w = { v0 + bias[c0], v1 + bias[c0 + 1] };
                    *(float2*)(g_k + (((size_t)(b * NH + h)) * SRC + s) * HD + d) = w;
                } else { // MODE == 3: V transposed scatter
                    int s = r >> 2, b = r & 3;
                    int h0 = c0 >> 6, d0 = c0 & 63;
                    int h1 = (c0 + 1) >> 6, d1 = (c0 + 1) & 63;
                    g_vt[(((size_t)(b * NH + h0)) * HD + d0) * SRC + s] = v0 + bias[c0];
                    g_vt[(((size_t)(b * NH + h1)) * HD + d1) * SRC + s] = v1 + bias[c0 + 1];
                }
            }
        }
    }
}

// ---------------------------------------------------------------------------
// softmax -> hard mask -> masked P in place, head-average into avg_out
// ---------------------------------------------------------------------------
__global__ void __launch_bounds__(256)
softmax_mask_avg_kernel(const float* __restrict__ hard, float* __restrict__ avg_out)
{
    const int t = blockIdx.x;
    const int b = blockIdx.y;
    const int tid = threadIdx.x;
    __shared__ float red[8];

    const float* mrow = hard + ((size_t)b * TGT + t) * SRC;
    float mask[4], avg[4] = {0.f, 0.f, 0.f, 0.f};
#pragma unroll
    for (int i = 0; i < 4; i++) mask[i] = mrow[tid + i * 256];

    for (int h = 0; h < NH; h++) {
        float* row = g_scores + ((size_t)(b * NH + h) * TGT + t) * SRC;
        float v[4];
#pragma unroll
        for (int i = 0; i < 4; i++) v[i] = row[tid + i * 256];

        float m = fmaxf(fmaxf(v[0], v[1]), fmaxf(v[2], v[3]));
#pragma unroll
        for (int o = 16; o; o >>= 1) m = fmaxf(m, __shfl_xor_sync(0xffffffffu, m, o));
        if ((tid & 31) == 0) red[tid >> 5] = m;
        __syncthreads();
        m = fmaxf(fmaxf(fmaxf(red[0], red[1]), fmaxf(red[2], red[3])),
                  fmaxf(fmaxf(red[4], red[5]), fmaxf(red[6], red[7])));
        __syncthreads();

        float e[4], s = 0.f;
#pragma unroll
        for (int i = 0; i < 4; i++) { e[i] = __expf(v[i] - m); s += e[i]; }
#pragma unroll
        for (int o = 16; o; o >>= 1) s += __shfl_xor_sync(0xffffffffu, s, o);
        if ((tid & 31) == 0) red[tid >> 5] = s;
        __syncthreads();
        s = red[0] + red[1] + red[2] + red[3] + red[4] + red[5] + red[6] + red[7];
        __syncthreads();

        const float inv = 1.0f / s;
#pragma unroll
        for (int i = 0; i < 4; i++) {
            float p = e[i] * inv * mask[i];
            row[tid + i * 256] = p;
            avg[i] += p;
        }
    }

    float* arow = avg_out + ((size_t)b * TGT + t) * SRC;
#pragma unroll
    for (int i = 0; i < 4; i++) arow[tid + i * 256] = avg[i] * (1.0f / NH);
}

// ---------------------------------------------------------------------------
extern "C" void kernel_launch(void* const* d_in, const int* in_sizes, int n_in,
                              void* d_out, int out_size)
{
    const float* query = (const float*)d_in[0];  // (T,B,E)
    const float* key   = (const float*)d_in[1];  // (S,B,E)
    const float* hard  = (const float*)d_in[2];  // (B,T,S)
    const float* W     = (const float*)d_in[3];  // (3E,E)
    const float* bias  = (const float*)d_in[4];  // (3E,)
    const float* Wo    = (const float*)d_in[5];  // (E,E)
    const float* bo    = (const float*)d_in[6];  // (E,)
    float* out = (float*)d_out;
    float* avg_out = out + (size_t)TGT * BSZb * EMB;

    const int MTB = TGT * BSZb;  // 4096

    // 1..3: QKV projections
    {
        dim3 grid(EMB / 128, MTB / 128);
        mma_gemm<128, 128, 2, 4, 1><<<grid, 256>>>(query, EMB, W, EMB, bias, nullptr, EMB);
        mma_gemm<128, 128, 2, 4, 2><<<grid, 256>>>(key, EMB, W + (size_t)EMB * EMB, EMB, bias + EMB, nullptr, EMB);
        mma_gemm<128, 128, 2, 4, 3><<<grid, 256>>>(key, EMB, W + (size_t)2 * EMB * EMB, EMB, bias + 2 * EMB, nullptr, EMB);
    }
    // 4: scores = Q @ K^T per (b,h)
    {
        dim3 grid(SRC / 128, TGT / 128, BSZb * NH);
        mma_gemm<128, 128, 2, 4, 0><<<grid, 256>>>(nullptr, HD, nullptr, HD, nullptr, nullptr, HD);
    }
    // 5: softmax + mask + head-average
    {
        dim3 grid(TGT, BSZb);
        softmax_mask_avg_kernel<<<grid, 256>>>(hard, avg_out);
    }
    // 6: ctx = P @ V per (b,h)
    {
        dim3 grid(1, TGT / 128, BSZb * NH);
        mma_gemm<128, 64, 4, 2, 4><<<grid, 256>>>(nullptr, SRC, nullptr, SRC, nullptr, nullptr, SRC);
    }
    // 7: out projection
    {
        dim3 grid(EMB / 128, MTB / 128);
        mma_gemm<128, 128, 2, 4, 5><<<grid, 256>>>(nullptr, EMB, Wo, EMB, bo, out, EMB);
    }
}

// round 4
// speedup vs baseline: 3.5713x; 1.4479x over previous
#include <cuda_runtime.h>
#include <cuda_fp16.h>
#include <cstdint>

#define TGT 1024
#define SRC 1024
#define BSZb 4
#define EMB 1024
#define NH 16
#define HD 64

// -------- device scratch (allocation-free rule: __device__ globals) --------
__device__ __half g_q[BSZb * NH * TGT * HD];        // (b,h,t,d) scaled, fp16
__device__ __half g_k[BSZb * NH * SRC * HD];        // (b,h,s,d) fp16
__device__ __half g_v[BSZb * NH * SRC * HD];        // (b,h,s,d) fp16
__device__ float  g_scores[(size_t)BSZb * NH * TGT * SRC]; // raw scores fp32
__device__ __half g_p[(size_t)BSZb * NH * TGT * SRC];      // masked P fp16
__device__ float  g_ctx[TGT * BSZb * EMB];          // (t,b,e) fp32

__device__ __forceinline__ uint32_t h2u(__half2 h) {
    return *reinterpret_cast<uint32_t*>(&h);
}

__device__ __forceinline__ void mma16(float* d, uint32_t a0, uint32_t a1,
                                      uint32_t a2, uint32_t a3,
                                      uint32_t b0, uint32_t b1) {
    asm volatile(
        "mma.sync.aligned.m16n8k16.row.col.f32.f16.f16.f32 "
        "{%0,%1,%2,%3}, {%4,%5,%6,%7}, {%8,%9}, {%0,%1,%2,%3};"
        : "+f"(d[0]), "+f"(d[1]), "+f"(d[2]), "+f"(d[3])
        : "r"(a0), "r"(a1), "r"(a2), "r"(a3), "r"(b0), "r"(b1));
}

// ---------------------------------------------------------------------------
// fp16 mma.sync GEMM: C[m,n] = sum_k A[m,k]*B[n,k]
// MODE: 0=scores 1=Qproj 2=Kproj 3=Vproj 4=PV->ctx 5=outproj
// A source: fp32 (modes 1,2,3,5) or fp16 (0,4). B: fp32 (1,2,3,5), fp16 (0),
// fp16-transposed-on-load (4). BK=16 (one k16 MMA step per chunk).
// ---------------------------------------------------------------------------
template <int BM, int BN, int WM, int WN, int MODE>
__global__ void __launch_bounds__(256)
mma_gemm(const float* __restrict__ A, int lda,
         const float* __restrict__ B, int ldb,
         const float* __restrict__ bias,
         float* __restrict__ C, int K)
{
    constexpr bool A_HALF = (MODE == 0 || MODE == 4);
    constexpr bool B_HALF = (MODE == 0);
    constexpr bool B_TRANS = (MODE == 4);     // B from g_v, transpose on load
    constexpr int WTM = BM / WM, WTN = BN / WN;
    constexpr int MT = WTM / 16, NT = WTN / 8;

    // SMEM: 16 halves (8 u32) per row, padded to 12 u32 (conflict-free frags)
    __shared__ uint32_t As[2][BM][12];
    __shared__ uint32_t Bs[2][BN][12];

    const int z = blockIdx.z;
    const __half* Aph = nullptr;
    const __half* Bph = nullptr;
    const float* Apf = nullptr;
    const float* Bpf = nullptr;
    if constexpr (MODE == 0) {
        Aph = g_q + (size_t)z * TGT * HD;
        Bph = g_k + (size_t)z * SRC * HD;
    } else if constexpr (MODE == 4) {
        Aph = g_p + (size_t)z * TGT * SRC;
        Bph = g_v + (size_t)z * SRC * HD;
    } else if constexpr (MODE == 5) {
        Apf = g_ctx;
        Bpf = B;
    } else {
        Apf = A;
        Bpf = B;
    }

    const int bm = blockIdx.y * BM;
    const int bn = blockIdx.x * BN;
    const int tid = threadIdx.x;
    const int lane = tid & 31;
    const int wid = tid >> 5;
    const int wm = wid / WN;
    const int wn = wid % WN;

    float acc[MT][NT][4];
#pragma unroll
    for (int i = 0; i < MT; i++)
#pragma unroll
        for (int j = 0; j < NT; j++)
#pragma unroll
            for (int q = 0; q < 4; q++) acc[i][j][q] = 0.0f;

    const int NC = K / 16;

    // ---- loaders (store chunk `ch` of A/B into buffer `buf`) ----
    auto storeA = [&](int buf, int ch, const uint4& hv, const float4* fv) {
        if constexpr (A_HALF) {
            int r = tid >> 1, h8 = tid & 1;
            *(uint4*)&As[buf][r][h8 * 4] = hv;
        } else {
#pragma unroll
            for (int it = 0; it < 2; it++) {
                int g = tid + it * 256, r = g >> 2, kq = g & 3;
                uint32_t p0 = h2u(__floats2half2_rn(fv[it].x, fv[it].y));
                uint32_t p1 = h2u(__floats2half2_rn(fv[it].z, fv[it].w));
                As[buf][r][kq * 2] = p0;
                As[buf][r][kq * 2 + 1] = p1;
            }
        }
        (void)ch;
    };

    // prefetch registers
    uint4 pha;  float4 pfa[2];
    uint4 phb;  float4 pfb[2];
    uint32_t ptv0, ptv1;

    auto fetchA = [&](int ch) {
        if constexpr (A_HALF) {
            int r = tid >> 1, h8 = tid & 1;
            pha = *(const uint4*)(Aph + (size_t)(bm + r) * lda + ch * 16 + h8 * 8);
        } else {
#pragma unroll
            for (int it = 0; it < 2; it++) {
                int g = tid + it * 256, r = g >> 2, kq = g & 3;
                pfa[it] = *(const float4*)(Apf + (size_t)(bm + r) * lda + ch * 16 + kq * 4);
            }
        }
    };
    auto fetchB = [&](int ch) {
        if constexpr (B_TRANS) {
            // read V[s][d], produce Bs[d][s-pairs]; 64 d x 16 s per chunk
            int dp = tid & 31, sp = tid >> 5;   // sp 0..7
            int s0 = ch * 16 + sp * 2;
            ptv0 = *(const uint32_t*)(Bph + (size_t)s0 * HD + dp * 2);
            ptv1 = *(const uint32_t*)(Bph + (size_t)(s0 + 1) * HD + dp * 2);
        } else if constexpr (B_HALF) {
            int r = tid >> 1, h8 = tid & 1;
            phb = *(const uint4*)(Bph + (size_t)(bn + r) * ldb + ch * 16 + h8 * 8);
        } else {
#pragma unroll
            for (int it = 0; it < 2; it++) {
                int g = tid + it * 256, r = g >> 2, kq = g & 3;
                pfb[it] = *(const float4*)(Bpf + (size_t)(bn + r) * ldb + ch * 16 + kq * 4);
            }
        }
    };
    auto storeB = [&](int buf) {
        if constexpr (B_TRANS) {
            int dp = tid & 31, sp = tid >> 5;
            Bs[buf][dp * 2][sp]     = __byte_perm(ptv0, ptv1, 0x5410);
            Bs[buf][dp * 2 + 1][sp] = __byte_perm(ptv0, ptv1, 0x7632);
        } else if constexpr (B_HALF) {
            int r = tid >> 1, h8 = tid & 1;
            *(uint4*)&Bs[buf][r][h8 * 4] = phb;
        } else {
#pragma unroll
            for (int it = 0; it < 2; it++) {
                int g = tid + it * 256, r = g >> 2, kq = g & 3;
                Bs[buf][r][kq * 2]     = h2u(__floats2half2_rn(pfb[it].x, pfb[it].y));
                Bs[buf][r][kq * 2 + 1] = h2u(__floats2half2_rn(pfb[it].z, pfb[it].w));
            }
        }
    };

    // chunk 0
    fetchA(0); fetchB(0);
    storeA(0, 0, pha, pfa); storeB(0);
    __syncthreads();

    for (int ch = 0; ch < NC; ch++) {
        const int buf = ch & 1;
        if (ch + 1 < NC) { fetchA(ch + 1); fetchB(ch + 1); }

        // compute one k16 step
        const int kq = lane & 3;
        uint32_t bf[NT][2];
#pragma unroll
        for (int nt = 0; nt < NT; nt++) {
            int n = wn * WTN + nt * 8 + (lane >> 2);
            bf[nt][0] = Bs[buf][n][kq];
            bf[nt][1] = Bs[buf][n][kq + 4];
        }
#pragma unroll
        for (int mt = 0; mt < MT; mt++) {
            int m = wm * WTM + mt * 16 + (lane >> 2);
            uint32_t a0 = As[buf][m][kq];
            uint32_t a1 = As[buf][m + 8][kq];
            uint32_t a2 = As[buf][m][kq + 4];
            uint32_t a3 = As[buf][m + 8][kq + 4];
#pragma unroll
            for (int nt = 0; nt < NT; nt++)
                mma16(acc[mt][nt], a0, a1, a2, a3, bf[nt][0], bf[nt][1]);
        }

        if (ch + 1 < NC) {
            storeA(buf ^ 1, ch + 1, pha, pfa);
            storeB(buf ^ 1);
            __syncthreads();
        }
    }

    // --- epilogue ---
#pragma unroll
    for (int mt = 0; mt < MT; mt++) {
#pragma unroll
        for (int nt = 0; nt < NT; nt++) {
            const int r0 = bm + wm * WTM + mt * 16 + (lane >> 2);
            const int c0 = bn + wn * WTN + nt * 8 + 2 * (lane & 3);
            const float* a4 = acc[mt][nt];

#pragma unroll
            for (int half = 0; half < 2; half++) {
                const int r = r0 + half * 8;
                const float v0 = a4[half * 2 + 0];
                const float v1 = a4[half * 2 + 1];

                if constexpr (MODE == 0) {
                    float2 w = { v0, v1 };
                    *(float2*)(g_scores + (size_t)z * TGT * SRC + (size_t)r * SRC + c0) = w;
                } else if constexpr (MODE == 4) {
                    int b = z >> 4, h = z & 15;
                    float2 w = { v0, v1 };
                    *(float2*)(g_ctx + ((size_t)r * BSZb + b) * EMB + h * HD + c0) = w;
                } else if constexpr (MODE == 5) {
                    float2 w = { v0 + bias[c0], v1 + bias[c0 + 1] };
                    *(float2*)(C + (size_t)r * EMB + c0) = w;
                } else if constexpr (MODE == 1) {
                    int t = r >> 2, b = r & 3, h = c0 >> 6, d = c0 & 63;
                    __half2 w = __floats2half2_rn((v0 + bias[c0]) * 0.125f,
                                                  (v1 + bias[c0 + 1]) * 0.125f);
                    *(__half2*)(g_q + (((size_t)(b * NH + h)) * TGT + t) * HD + d) = w;
                } else if constexpr (MODE == 2) {
                    int s = r >> 2, b = r & 3, h = c0 >> 6, d = c0 & 63;
                    __half2 w = __floats2half2_rn(v0 + bias[c0], v1 + bias[c0 + 1]);
                    *(__half2*)(g_k + (((size_t)(b * NH + h)) * SRC + s) * HD + d) = w;
                } else { // MODE == 3: V, same layout as K
                    int s = r >> 2, b = r & 3, h = c0 >> 6, d = c0 & 63;
                    __half2 w = __floats2half2_rn(v0 + bias[c0], v1 + bias[c0 + 1]);
                    *(__half2*)(g_v + (((size_t)(b * NH + h)) * SRC + s) * HD + d) = w;
                }
            }
        }
    }
}

// ---------------------------------------------------------------------------
// softmax -> hard mask -> P (fp16) to g_p, head-average (fp32) to avg_out
// ---------------------------------------------------------------------------
__global__ void __launch_bounds__(256)
softmax_mask_avg_kernel(const float* __restrict__ hard, float* __restrict__ avg_out)
{
    const int t = blockIdx.x;
    const int b = blockIdx.y;
    const int tid = threadIdx.x;
    const int c = tid * 4;
    __shared__ float red[8];

    const float* mrow = hard + ((size_t)b * TGT + t) * SRC;
    float4 mask = *(const float4*)(mrow + c);
    float4 avg = { 0.f, 0.f, 0.f, 0.f };

    for (int h = 0; h < NH; h++) {
        const size_t roff = ((size_t)(b * NH + h) * TGT + t) * SRC;
        float4 v = *(const float4*)(g_scores + roff + c);

        float m = fmaxf(fmaxf(v.x, v.y), fmaxf(v.z, v.w));
#pragma unroll
        for (int o = 16; o; o >>= 1) m = fmaxf(m, __shfl_xor_sync(0xffffffffu, m, o));
        if ((tid & 31) == 0) red[tid >> 5] = m;
        __syncthreads();
        m = fmaxf(fmaxf(fmaxf(red[0], red[1]), fmaxf(red[2], red[3])),
                  fmaxf(fmaxf(red[4], red[5]), fmaxf(red[6], red[7])));
        __syncthreads();

        float e0 = __expf(v.x - m), e1 = __expf(v.y - m);
        float e2 = __expf(v.z - m), e3 = __expf(v.w - m);
        float s = e0 + e1 + e2 + e3;
#pragma unroll
        for (int o = 16; o; o >>= 1) s += __shfl_xor_sync(0xffffffffu, s, o);
        if ((tid & 31) == 0) red[tid >> 5] = s;
        __syncthreads();
        s = red[0] + red[1] + red[2] + red[3] + red[4] + red[5] + red[6] + red[7];
        __syncthreads();

        const float inv = 1.0f / s;
        float p0 = e0 * inv * mask.x, p1 = e1 * inv * mask.y;
        float p2 = e2 * inv * mask.z, p3 = e3 * inv * mask.w;
        avg.x += p0; avg.y += p1; avg.z += p2; avg.w += p3;

        uint2 w = { *(uint32_t*)&(__half2&)*(__half2[1]){__floats2half2_rn(p0, p1)},
                    0 };
        __half2 lo = __floats2half2_rn(p0, p1);
        __half2 hi = __floats2half2_rn(p2, p3);
        w.x = *reinterpret_cast<uint32_t*>(&lo);
        w.y = *reinterpret_cast<uint32_t*>(&hi);
        *(uint2*)(g_p + roff + c) = w;
    }

    float* arow = avg_out + ((size_t)b * TGT + t) * SRC;
    float4 aw = { avg.x * (1.0f / NH), avg.y * (1.0f / NH),
                  avg.z * (1.0f / NH), avg.w * (1.0f / NH) };
    *(float4*)(arow + c) = aw;
}

// ---------------------------------------------------------------------------
extern "C" void kernel_launch(void* const* d_in, const int* in_sizes, int n_in,
                              void* d_out, int out_size)
{
    const float* query = (const float*)d_in[0];  // (T,B,E)
    const float* key   = (const float*)d_in[1];  // (S,B,E)
    const float* hard  = (const float*)d_in[2];  // (B,T,S)
    const float* W     = (const float*)d_in[3];  // (3E,E)
    const float* bias  = (const float*)d_in[4];  // (3E,)
    const float* Wo    = (const float*)d_in[5];  // (E,E)
    const float* bo    = (const float*)d_in[6];  // (E,)
    float* out = (float*)d_out;
    float* avg_out = out + (size_t)TGT * BSZb * EMB;

    const int MTB = TGT * BSZb;  // 4096

    // 1..3: QKV projections
    {
        dim3 grid(EMB / 128, MTB / 128);
        mma_gemm<128, 128, 2, 4, 1><<<grid, 256>>>(query, EMB, W, EMB, bias, nullptr, EMB);
        mma_gemm<128, 128, 2, 4, 2><<<grid, 256>>>(key, EMB, W + (size_t)EMB * EMB, EMB, bias + EMB, nullptr, EMB);
        mma_gemm<128, 128, 2, 4, 3><<<grid, 256>>>(key, EMB, W + (size_t)2 * EMB * EMB, EMB, bias + 2 * EMB, nullptr, EMB);
    }
    // 4: scores = Q @ K^T per (b,h)
    {
        dim3 grid(SRC / 128, TGT / 128, BSZb * NH);
        mma_gemm<128, 128, 2, 4, 0><<<grid, 256>>>(nullptr, HD, nullptr, HD, nullptr, nullptr, HD);
    }
    // 5: softmax + mask + head-average
    {
        dim3 grid(TGT, BSZb);
        softmax_mask_avg_kernel<<<grid, 256>>>(hard, avg_out);
    }
    // 6: ctx = P @ V per (b,h)
    {
        dim3 grid(1, TGT / 128, BSZb * NH);
        mma_gemm<128, 64, 4, 2, 4><<<grid, 256>>>(nullptr, SRC, nullptr, HD, nullptr, nullptr, SRC);
    }
    // 7: out projection
    {
        dim3 grid(EMB / 128, MTB / 128);
        mma_gemm<128, 128, 2, 4, 5><<<grid, 256>>>(nullptr, EMB, Wo, EMB, bo, out, EMB);
    }
}